// round 12
// baseline (speedup 1.0000x reference)
#include <cuda_runtime.h>
#include <cuda_fp16.h>
#include <cstdint>

// ---------------------------------------------------------------------------
// MedianConvolution: out[n,c] = lower_median_k( (x @ W^T)[nbrs[n,k], c] )
// N=100000, K=32, IN_C=128, OUT_C=64.  nbrs is int32 (JAX demotes int64).
// h kept in fp16; median runs packed half2 (78.4us, protected).
// GEMM: 8x8 micro-tile FFMA2 — 1.0 B LDS per FMA (was 1.5), LDS floor and
// FFMA2 floor both ~43k cyc.
// ---------------------------------------------------------------------------

#define N_NODES 100000
#define IN_C    128
#define OUT_C   64
#define KNBR    32

// gemm tile config: block = 256 rows x 64 cols, thread = 8x8
#define BM 256
#define BK 16
#define XPAD 4
#define WPAD 4

// intermediate h = x @ W^T in fp16 (12.8 MB static scratch — allocation-free)
__device__ __align__(16) __half g_h[N_NODES * OUT_C];

typedef unsigned long long u64;

__device__ __forceinline__ u64 pk2(float a, float b) {
    u64 r;
    asm("mov.b64 %0, {%1, %2};" : "=l"(r) : "f"(a), "f"(b));
    return r;
}
__device__ __forceinline__ void upk2(u64 p, float& a, float& b) {
    asm("mov.b64 {%0, %1}, %2;" : "=f"(a), "=f"(b) : "l"(p));
}
// acc = x2 * w2 + acc, per-lane fp32 (FFMA2)
__device__ __forceinline__ void fma2(u64& acc, u64 x2, u64 w2) {
    asm("fma.rn.f32x2 %0, %1, %2, %0;" : "+l"(acc) : "l"(x2), "l"(w2));
}

// ---------------------------------------------------------------------------
// Kernel 1: h = x @ W^T.  Block tile 256x64, thread = 8 rows x 8 cols as
// 4 row-pair FFMA2 accumulators x 8 cols (32 u64).  Per k-step: 4 LDS.128
// (64B) for 64 FMAs.  xs[k][row]: adjacent rows -> row-pairs pre-packed.
// ---------------------------------------------------------------------------
__global__ __launch_bounds__(256) void gemm_kernel(
    const float* __restrict__ x,
    const float* __restrict__ W,
    int n)
{
    __shared__ float wt[IN_C][OUT_C + WPAD];   // 34.8 KB, stride 272B (16B-mult)
    __shared__ float xs[BK][BM + XPAD];        // 16.6 KB, stride 1040B (16B-mult)

    const int tid = threadIdx.x;
    const int tx = tid & 7;                 // col group: cols tx*8..+7
    const int ty = tid >> 3;                // row group: rows ty*8..+7
    const int rowBase = blockIdx.x * BM;

    for (int e = tid; e < OUT_C * IN_C; e += 256) {
        int c = e >> 7, k = e & 127;
        wt[k][c] = W[e];
    }

    u64 acc2[4][8];                         // [row-pair][col]
#pragma unroll
    for (int i = 0; i < 4; i++)
#pragma unroll
        for (int j = 0; j < 8; j++) acc2[i][j] = 0ull;

    for (int kb = 0; kb < IN_C / BK; kb++) {
        __syncthreads();   // first iter: covers W staging; later: xs reuse
        // stage x tile [256 rows][16 k]: 1024 float4, 4 per thread, coalesced
#pragma unroll
        for (int i = 0; i < 4; i++) {
            int e   = tid + i * 256;        // 0..1023
            int row = e >> 2;               // 0..255
            int q   = e & 3;                // float4 within 16-k chunk
            int grow = rowBase + row;
            float4 v = make_float4(0.f, 0.f, 0.f, 0.f);
            if (grow < n)
                v = __ldg(reinterpret_cast<const float4*>(
                        x + (size_t)grow * IN_C + kb * BK) + q);
            xs[q * 4 + 0][row] = v.x;
            xs[q * 4 + 1][row] = v.y;
            xs[q * 4 + 2][row] = v.z;
            xs[q * 4 + 3][row] = v.w;
        }
        __syncthreads();

#pragma unroll
        for (int k = 0; k < BK; k++) {
            const ulonglong2 xA =
                *reinterpret_cast<const ulonglong2*>(&xs[k][ty * 8]);
            const ulonglong2 xB =
                *reinterpret_cast<const ulonglong2*>(&xs[k][ty * 8 + 4]);
            const float4 wa =
                *reinterpret_cast<const float4*>(&wt[kb * BK + k][tx * 8]);
            const float4 wb =
                *reinterpret_cast<const float4*>(&wt[kb * BK + k][tx * 8 + 4]);

            const u64 xp[4] = { xA.x, xA.y, xB.x, xB.y };
            const u64 w2[8] = { pk2(wa.x, wa.x), pk2(wa.y, wa.y),
                                pk2(wa.z, wa.z), pk2(wa.w, wa.w),
                                pk2(wb.x, wb.x), pk2(wb.y, wb.y),
                                pk2(wb.z, wb.z), pk2(wb.w, wb.w) };
#pragma unroll
            for (int i = 0; i < 4; i++)
#pragma unroll
                for (int c = 0; c < 8; c++)
                    fma2(acc2[i][c], xp[i], w2[c]);
        }
    }

    // epilogue: unpack row-pairs, convert to fp16, one 16B store per row
#pragma unroll
    for (int i = 0; i < 4; i++) {
        float lo[8], hi[8];
#pragma unroll
        for (int c = 0; c < 8; c++) upk2(acc2[i][c], lo[c], hi[c]);

        int r0 = rowBase + ty * 8 + 2 * i;
        if (r0 < n) {
            __half2* o = reinterpret_cast<__half2*>(
                g_h + (size_t)r0 * OUT_C + tx * 8);
            o[0] = __floats2half2_rn(lo[0], lo[1]);
            o[1] = __floats2half2_rn(lo[2], lo[3]);
            o[2] = __floats2half2_rn(lo[4], lo[5]);
            o[3] = __floats2half2_rn(lo[6], lo[7]);
        }
        int r1 = r0 + 1;
        if (r1 < n) {
            __half2* o = reinterpret_cast<__half2*>(
                g_h + (size_t)r1 * OUT_C + tx * 8);
            o[0] = __floats2half2_rn(hi[0], hi[1]);
            o[1] = __floats2half2_rn(hi[2], hi[3]);
            o[2] = __floats2half2_rn(hi[4], hi[5]);
            o[3] = __floats2half2_rn(hi[6], hi[7]);
        }
    }
}

// ---------------------------------------------------------------------------
// Kernel 2: gather + lower-median over K=32, packed half2 (2 channels/thread).
// 256 threads/block = 8 nodes x 32 threads; warp = 32 channel-pairs of one
// node -> each neighbor gather is exactly one 128B line (L2-resident).
// Median: explicit Batcher odd-even mergesort (63 comparators) per half,
// then 16th-smallest of the merge via max_i min(A[i], B[15-i]).
// Measured 78.4us, alu-bound.  DO NOT TOUCH.
// ---------------------------------------------------------------------------
__device__ __forceinline__ void cas2(__half2& a, __half2& b) {
    __half2 lo = __hmin2(a, b);
    b = __hmax2(a, b);
    a = lo;
}

#define S(i,j) cas2(v[i], v[j])
__device__ __forceinline__ void bsort16h(__half2* v) {
    // L1
    S(0,1); S(2,3); S(4,5); S(6,7); S(8,9); S(10,11); S(12,13); S(14,15);
    // L2
    S(0,2); S(1,3); S(4,6); S(5,7); S(8,10); S(9,11); S(12,14); S(13,15);
    // L3
    S(1,2); S(5,6); S(9,10); S(13,14);
    // L4
    S(0,4); S(1,5); S(2,6); S(3,7); S(8,12); S(9,13); S(10,14); S(11,15);
    // L5
    S(2,4); S(3,5); S(10,12); S(11,13);
    // L6
    S(1,2); S(3,4); S(5,6); S(9,10); S(11,12); S(13,14);
    // L7
    S(0,8); S(1,9); S(2,10); S(3,11); S(4,12); S(5,13); S(6,14); S(7,15);
    // L8
    S(4,8); S(5,9); S(6,10); S(7,11);
    // L9
    S(2,4); S(3,5); S(6,8); S(7,9); S(10,12); S(11,13);
    // L10
    S(1,2); S(3,4); S(5,6); S(7,8); S(9,10); S(11,12); S(13,14);
}
#undef S

__global__ __launch_bounds__(256) void median_kernel(
    const int* __restrict__ nbrs,      // int32
    float* __restrict__ out,
    int n)
{
    __shared__ int snb[8 * KNBR];

    const int base = blockIdx.x * 8;
    const int tid = threadIdx.x;

    {
        int node = base + (tid >> 5);
        int idx = (node < n) ? nbrs[(size_t)node * KNBR + (tid & 31)] : 0;
        idx = max(0, min(idx, n - 1));   // defensive clamp
        snb[tid] = idx;
    }
    __syncthreads();

    const int ty = tid >> 5;   // node within block (0..7)
    const int tx = tid & 31;   // channel-pair index (channels 2tx, 2tx+1)
    const int node = base + ty;
    if (node >= n) return;

    const __half2* h2 = reinterpret_cast<const __half2*>(g_h);

    __half2 v[KNBR];
#pragma unroll
    for (int k = 0; k < KNBR; k++) {
        int idx = snb[ty * KNBR + k];                 // smem broadcast
        v[k] = __ldg(&h2[(size_t)idx * (OUT_C / 2) + tx]);
    }

    bsort16h(v);
    bsort16h(v + 16);

    // 16th smallest (rank index 15) of the merge of two sorted 16-arrays,
    // computed independently in both half lanes
    __half2 med = __hmin2(v[0], v[31]);
#pragma unroll
    for (int i = 1; i < 16; i++)
        med = __hmax2(med, __hmin2(v[i], v[31 - i]));

    float2 f = __half22float2(med);
    float2* o = reinterpret_cast<float2*>(out + (size_t)node * OUT_C) + tx;
    *o = f;
}

// ---------------------------------------------------------------------------
extern "C" void kernel_launch(void* const* d_in, const int* in_sizes, int n_in,
                              void* d_out, int out_size) {
    const float* x    = (const float*)d_in[0];
    const int*   nbrs = (const int*)d_in[1];
    const float* W    = (const float*)d_in[2];
    float*       out  = (float*)d_out;

    const int n = in_sizes[0] / IN_C;   // 100000

    gemm_kernel<<<(n + BM - 1) / BM, 256>>>(x, W, n);
    median_kernel<<<(n + 7) / 8, 256>>>(nbrs, out, n);
}